// round 13
// baseline (speedup 1.0000x reference)
#include <cuda_runtime.h>
#include <cuda_fp16.h>
#include <math.h>

// Problem constants
#define BB   16
#define TT   512
#define HH   384
#define FF   384
#define KK3  3
#define DMAX 8
#define LL   (TT * DMAX)          // 4096
#define BT   (BB * TT)            // 8192
#define KKT  (HH * KK3)           // 1152 unified reduction dim
#define H4   (HH / 4)             // 96 float4 per row
#define OUT_OFF ((size_t)BB * LL * HH)   // length[] offset in d_out

// GEMM tiling (R10 best config): BM=128, BN=64, BK=64, 256 threads, 2-stage
#define BM 128
#define BN 64
#define BK 64
#define NKT (KKT / BK)            // 18 k-iterations

// Scratch (static device globals; no allocation allowed)
__device__ __half g_wt1h[FF * KKT];     // conv1 weights, f-major, pair-permuted fp16
__device__ __half g_wt2h[FF * KKT];     // conv2 weights, same layout
__device__ __half g_xh[BT * HH];        // x, fp16 + pair-permuted
__device__ float  g_h1[BT * FF];        // conv1 out (fp32)
__device__ __half g_h1h[BT * FF];       // ln_gelu(conv1) fp16 pair-permuted
__device__ float  g_h2[BT * FF];        // conv2 output (fp32)
__device__ int    g_tok[BB * LL];       // token index per expanded position (-1 = pad)

// ---------------------------------------------------------------------------
// half-index permutation: within each 16-half block, k-pairs interleaved
// [0,4,1,5,2,6,3,7] so one LDS.64 yields pairs (q, q+4) = one mma fragment.
// ---------------------------------------------------------------------------
__device__ __forceinline__ int perm8(int c) {
    int u = c & 7;
    return (c & ~7) | ((u < 4) ? (u << 1) : (((u - 4) << 1) | 1));
}
__device__ __forceinline__ int permH(int k) {
    return (perm8(k >> 1) << 1) | (k & 1);
}

// cp.async 16B with zero-fill when sz==0
__device__ __forceinline__ void cp16(void* dst, const void* src, int sz) {
    unsigned d = (unsigned)__cvta_generic_to_shared(dst);
    asm volatile("cp.async.cg.shared.global [%0], [%1], 16, %2;\n"
                 :: "r"(d), "l"(src), "r"(sz));
}

// ---------------------------------------------------------------------------
// Merged prep: x conversion + both weight transposes in one launch.
// ---------------------------------------------------------------------------
#define NX  (BT * HH)             // 3,145,728
#define NW  (FF * HH * KK3)       // 442,368
#define NPREP (NX + 2 * NW)       // 4,030,464 = 15744 * 256

__global__ void prep_kernel(const float* __restrict__ x, __half* __restrict__ xh,
                            const float* __restrict__ w1, const float* __restrict__ w2,
                            __half* __restrict__ o1, __half* __restrict__ o2) {
    int i = blockIdx.x * 256 + threadIdx.x;
    if (i < NX) {
        int m = i / HH, c = i % HH;
        xh[m * HH + permH(c)] = __float2half_rn(x[i]);
        return;
    }
    i -= NX;
    const float* w = w1; __half* o = o1;
    if (i >= NW) { i -= NW; w = w2; o = o2; }
    int f   = i / (HH * 3);
    int rem = i % (HH * 3);
    int c   = rem / 3;
    int tap = rem % 3;
    o[f * KKT + tap * HH + permH(c)] = __float2half_rn(w[i]);
}

__device__ __forceinline__ void mma_f16(float c[4], const unsigned a[4], const unsigned b[2]) {
    asm volatile(
        "mma.sync.aligned.m16n8k16.row.col.f32.f16.f16.f32 "
        "{%0,%1,%2,%3}, {%4,%5,%6,%7}, {%8,%9}, {%0,%1,%2,%3};\n"
        : "+f"(c[0]), "+f"(c[1]), "+f"(c[2]), "+f"(c[3])
        : "r"(a[0]), "r"(a[1]), "r"(a[2]), "r"(a[3]), "r"(b[0]), "r"(b[1]));
}

// ---------------------------------------------------------------------------
// Conv-as-GEMM, fp16 m16n8k16, cp.async double-buffered, LDS.64 fragments.
// Grid (6, 64) = 384 CTAs, 256 threads (8 warps: 4M x 2N), 48 KB static smem.
// __launch_bounds__(256, 3): 3 CTAs/SM -> 24 warps resident, single wave.
// ---------------------------------------------------------------------------
__global__ void __launch_bounds__(256, 3) conv_gemm_kernel(
    const __half* __restrict__ Axh, const __half* __restrict__ Bwh,
    const float* __restrict__ bias, float* __restrict__ C) {
    __shared__ __align__(16) uint2 SA[2][BM][16];   // 32 KB
    __shared__ __align__(16) uint2 SB[2][BN][16];   // 16 KB

    const int tid  = threadIdx.x;
    const int lane = tid & 31;
    const int warp = tid >> 5;
    const int m0w  = (warp & 3) * 32;
    const int n0w  = (warp >> 2) * 32;
    const int m0   = blockIdx.y * BM;
    const int f0   = blockIdx.x * BN;
    const int b    = m0 >> 9;
    const int t0   = m0 & (TT - 1);

    const int r = lane >> 2;
    const int q = lane & 3;

    float acc[2][4][4];
#pragma unroll
    for (int mt = 0; mt < 2; mt++)
#pragma unroll
        for (int nt = 0; nt < 4; nt++)
#pragma unroll
            for (int i = 0; i < 4; i++) acc[mt][nt][i] = 0.0f;

    const int amr[4] = { tid >> 3, (tid + 256) >> 3, (tid + 512) >> 3, (tid + 768) >> 3 };
    const int at     = tid & 7;
    const int bnr[2] = { tid >> 3, (tid + 256) >> 3 };

#define LOAD_TILE(KT, BUF) do {                                                \
        const int kk0 = (KT) * BK;                                             \
        const int tap = kk0 / HH;                                              \
        const int c0  = kk0 - tap * HH;                                        \
        _Pragma("unroll")                                                      \
        for (int i = 0; i < 4; i++) {                                          \
            const int m    = amr[i];                                           \
            const int trow = t0 + m + tap - 1;                                 \
            const int ok   = (trow >= 0 && trow < TT);                         \
            const __half* src = Axh +                                          \
                (size_t)((b << 9) + (ok ? trow : 0)) * HH + c0 + 8 * at;       \
            cp16(&SA[BUF][m][(2 * at) ^ ((m & 3) << 2)], src, ok ? 16 : 0);    \
        }                                                                      \
        _Pragma("unroll")                                                      \
        for (int i = 0; i < 2; i++) {                                          \
            const int n = bnr[i];                                              \
            const __half* src = Bwh + (size_t)(f0 + n) * KKT + kk0 + 8 * at;   \
            cp16(&SB[BUF][n][(2 * at) ^ ((n & 3) << 2)], src, 16);             \
        }                                                                      \
        asm volatile("cp.async.commit_group;\n");                              \
    } while (0)

    LOAD_TILE(0, 0);

    for (int kt = 0; kt < NKT; kt++) {
        const int cur = kt & 1;
        if (kt + 1 < NKT) {
            LOAD_TILE(kt + 1, cur ^ 1);
            asm volatile("cp.async.wait_group 1;\n");
        } else {
            asm volatile("cp.async.wait_group 0;\n");
        }
        __syncthreads();

#pragma unroll
        for (int s = 0; s < 4; s++) {
            unsigned a[2][4], bf[4][2];
#pragma unroll
            for (int mt = 0; mt < 2; mt++) {
                const int mr  = m0w + mt * 16 + r;
                const int idx = ((s ^ (mr & 3)) << 2) | q;
                const uint2 va0 = SA[cur][mr][idx];
                const uint2 va1 = SA[cur][mr + 8][idx];
                a[mt][0] = va0.x; a[mt][1] = va1.x; a[mt][2] = va0.y; a[mt][3] = va1.y;
            }
#pragma unroll
            for (int nt = 0; nt < 4; nt++) {
                const int nc  = n0w + nt * 8 + r;
                const uint2 vb = SB[cur][nc][((s ^ (nc & 3)) << 2) | q];
                bf[nt][0] = vb.x; bf[nt][1] = vb.y;
            }
#pragma unroll
            for (int mt = 0; mt < 2; mt++)
#pragma unroll
                for (int nt = 0; nt < 4; nt++)
                    mma_f16(acc[mt][nt], a[mt], bf[nt]);
        }
        __syncthreads();
    }

#pragma unroll
    for (int mt = 0; mt < 2; mt++) {
        const int gm0 = m0 + m0w + mt * 16 + r;
#pragma unroll
        for (int nt = 0; nt < 4; nt++) {
            const int gf = f0 + n0w + nt * 8 + 2 * q;
            const float2 bvv = *reinterpret_cast<const float2*>(bias + gf);
            float2 o0, o1;
            o0.x = acc[mt][nt][0] + bvv.x;
            o0.y = acc[mt][nt][1] + bvv.y;
            o1.x = acc[mt][nt][2] + bvv.x;
            o1.y = acc[mt][nt][3] + bvv.y;
            *reinterpret_cast<float2*>(C + (size_t)gm0 * FF + gf) = o0;
            *reinterpret_cast<float2*>(C + (size_t)(gm0 + 8) * FF + gf) = o1;
        }
    }
#undef LOAD_TILE
}

// ---------------------------------------------------------------------------
__device__ __forceinline__ float warp_sum(float v) {
#pragma unroll
    for (int o = 16; o > 0; o >>= 1) v += __shfl_xor_sync(0xffffffffu, v, o);
    return v;
}

__device__ __forceinline__ float gelu_exact(float y) {
    return 0.5f * y * (1.0f + erff(y * 0.70710678118654752f));
}

// LayerNorm + exact GELU; fp32 in, fp16 pair-permuted out. warp-per-row.
__global__ void __launch_bounds__(256) ln_gelu_kernel(
    const float* __restrict__ h, const float* __restrict__ g, const float* __restrict__ bb,
    __half* __restrict__ oh) {
    const int row  = blockIdx.x * 8 + (threadIdx.x >> 5);
    const int lane = threadIdx.x & 31;
    const float* p = h + (size_t)row * FF;
    __half* po = oh + (size_t)row * FF;
    float v[12];
    float s = 0.0f;
#pragma unroll
    for (int i = 0; i < 12; i++) { v[i] = p[lane + 32 * i]; s += v[i]; }
    const float mu = warp_sum(s) * (1.0f / FF);
    float s2 = 0.0f;
#pragma unroll
    for (int i = 0; i < 12; i++) { v[i] -= mu; s2 += v[i] * v[i]; }
    const float rs = rsqrtf(warp_sum(s2) * (1.0f / FF) + 1e-5f);
#pragma unroll
    for (int i = 0; i < 12; i++) {
        const int c = lane + 32 * i;
        po[permH(c)] = __float2half_rn(gelu_exact(v[i] * rs * g[c] + bb[c]));
    }
}

// LayerNorm + GELU + linear(384->1) + ReLU -> length[row]. warp-per-row.
__global__ void __launch_bounds__(256) ln_gelu_lin_kernel(
    const float* __restrict__ h, const float* __restrict__ g, const float* __restrict__ bb,
    const float* __restrict__ lw, const float* __restrict__ lb, float* __restrict__ lenout) {
    const int row  = blockIdx.x * 8 + (threadIdx.x >> 5);
    const int lane = threadIdx.x & 31;
    const float* p = h + (size_t)row * FF;
    float v[12];
    float s = 0.0f;
#pragma unroll
    for (int i = 0; i < 12; i++) { v[i] = p[lane + 32 * i]; s += v[i]; }
    const float mu = warp_sum(s) * (1.0f / FF);
    float s2 = 0.0f;
#pragma unroll
    for (int i = 0; i < 12; i++) { v[i] -= mu; s2 += v[i] * v[i]; }
    const float rs = rsqrtf(warp_sum(s2) * (1.0f / FF) + 1e-5f);
    float d = 0.0f;
#pragma unroll
    for (int i = 0; i < 12; i++) {
        const int c = lane + 32 * i;
        d += gelu_exact(v[i] * rs * g[c] + bb[c]) * lw[c];
    }
    const float dot = warp_sum(d);
    if (lane == 0) lenout[row] = fmaxf(dot + lb[0], 0.0f);
}

// ---------------------------------------------------------------------------
// Duration scan + token map. One block per batch, 512 threads.
// ---------------------------------------------------------------------------
__global__ void __launch_bounds__(512) build_tok_kernel(
    const float* __restrict__ td, int* __restrict__ tok) {
    __shared__ int sc[TT];
    const int b = blockIdx.x, t = threadIdx.x;
    const int d = (int)rintf(expf(td[b * TT + t]));
    sc[t] = d;
    __syncthreads();
    for (int off = 1; off < TT; off <<= 1) {
        int v = sc[t];
        int add = (t >= off) ? sc[t - off] : 0;
        __syncthreads();
        sc[t] = v + add;
        __syncthreads();
    }
    const int end = sc[t];
    const int start = end - d;
    for (int l = start; l < end; l++) tok[b * LL + l] = t;
    __syncthreads();
    const int total = sc[TT - 1];
    for (int l = total + t; l < LL; l += TT) tok[b * LL + l] = -1;
}

// ---------------------------------------------------------------------------
// Expansion: out[b,l,:] = x[b,tok[b][l],:] (or zeros). float4 per thread.
// ---------------------------------------------------------------------------
__global__ void __launch_bounds__(256) expand_kernel(
    const float* __restrict__ x, const int* __restrict__ tok, float* __restrict__ out) {
    const unsigned idx = blockIdx.x * 256u + threadIdx.x;
    const int h4 = idx % H4;
    const int l  = (idx / H4) & (LL - 1);
    const int b  = idx / (H4 * LL);
    const int t  = tok[b * LL + l];
    float4 v = make_float4(0.f, 0.f, 0.f, 0.f);
    if (t >= 0)
        v = reinterpret_cast<const float4*>(x)[(size_t)(b * TT + t) * H4 + h4];
    reinterpret_cast<float4*>(out)[idx] = v;
}

// ---------------------------------------------------------------------------
extern "C" void kernel_launch(void* const* d_in, const int* in_sizes, int n_in,
                              void* d_out, int out_size) {
    const float* x   = (const float*)d_in[0];
    const float* td  = (const float*)d_in[1];
    const float* w1  = (const float*)d_in[2];
    const float* b1  = (const float*)d_in[3];
    const float* g1  = (const float*)d_in[4];
    const float* bb1 = (const float*)d_in[5];
    const float* w2  = (const float*)d_in[6];
    const float* b2  = (const float*)d_in[7];
    const float* g2  = (const float*)d_in[8];
    const float* bb2 = (const float*)d_in[9];
    const float* lw  = (const float*)d_in[10];
    const float* lb  = (const float*)d_in[11];

    float* out = (float*)d_out;
    float* lenout = out + OUT_OFF;

    __half *wt1p, *wt2p, *xhp, *h1hp;
    float *h1p, *h2p;
    int* tokp;
    cudaGetSymbolAddress((void**)&wt1p, g_wt1h);
    cudaGetSymbolAddress((void**)&wt2p, g_wt2h);
    cudaGetSymbolAddress((void**)&xhp,  g_xh);
    cudaGetSymbolAddress((void**)&h1p,  g_h1);
    cudaGetSymbolAddress((void**)&h1hp, g_h1h);
    cudaGetSymbolAddress((void**)&h2p,  g_h2);
    cudaGetSymbolAddress((void**)&tokp, g_tok);

    // one-time side-stream + bridge events (host resources only; no device mem)
    static cudaStream_t s2 = nullptr;
    static cudaEvent_t evFork = nullptr, evJoin = nullptr;
    if (s2 == nullptr) {
        cudaStreamCreateWithFlags(&s2, cudaStreamNonBlocking);
        cudaEventCreateWithFlags(&evFork, cudaEventDisableTiming);
        cudaEventCreateWithFlags(&evJoin, cudaEventDisableTiming);
    }

    // fork: independent chain (td -> tok -> expand) on s2
    cudaEventRecord(evFork, 0);
    cudaStreamWaitEvent(s2, evFork, 0);
    build_tok_kernel<<<BB, TT, 0, s2>>>(td, tokp);
    expand_kernel<<<(BB * LL * H4) / 256, 256, 0, s2>>>(x, tokp, out);
    cudaEventRecord(evJoin, s2);

    // main chain: prep -> conv1 -> ln -> conv2 -> ln+lin
    prep_kernel<<<NPREP / 256, 256>>>(x, xhp, w1, w2, wt1p, wt2p);

    dim3 ggrid(FF / BN, BT / BM);   // (6, 64) = 384 CTAs
    conv_gemm_kernel<<<ggrid, 256>>>(xhp, wt1p, b1, h1p);
    ln_gelu_kernel<<<BT / 8, 256>>>(h1p, g1, bb1, h1hp);
    conv_gemm_kernel<<<ggrid, 256>>>(h1hp, wt2p, b2, h2p);
    ln_gelu_lin_kernel<<<BT / 8, 256>>>(h2p, g2, bb2, lw, lb, lenout);

    // join: main stream waits for the expansion branch
    cudaStreamWaitEvent(0, evJoin, 0);
}

// round 14
// speedup vs baseline: 1.4370x; 1.4370x over previous
#include <cuda_runtime.h>
#include <cuda_fp16.h>
#include <math.h>

// Problem constants
#define BB   16
#define TT   512
#define HH   384
#define FF   384
#define KK3  3
#define DMAX 8
#define LL   (TT * DMAX)          // 4096
#define BT   (BB * TT)            // 8192
#define KKT  (HH * KK3)           // 1152 unified reduction dim
#define H4   (HH / 4)             // 96 float4 per row
#define OUT_OFF ((size_t)BB * LL * HH)   // length[] offset in d_out

// GEMM tiling (R10 best config): BM=128, BN=64, BK=64, 256 threads, 2-stage
#define BM 128
#define BN 64
#define BK 64
#define NKT (KKT / BK)            // 18 k-iterations

// Scratch (static device globals; no allocation allowed)
__device__ __half g_wt1h[FF * KKT];     // conv1 weights, f-major, pair-permuted fp16
__device__ __half g_wt2h[FF * KKT];     // conv2 weights, same layout
__device__ __half g_xh[BT * HH];        // x, fp16 + pair-permuted
__device__ float  g_h1[BT * FF];        // conv1 out (fp32)
__device__ __half g_h1h[BT * FF];       // ln_gelu(conv1) fp16 pair-permuted
__device__ float  g_h2[BT * FF];        // conv2 output (fp32)
__device__ int    g_tok[BB * LL];       // token index per expanded position (-1 = pad)

// ---------------------------------------------------------------------------
// half-index permutation: within each 16-half block, k-pairs interleaved
// [0,4,1,5,2,6,3,7] so one LDS.64 yields pairs (q, q+4) = one mma fragment.
// ---------------------------------------------------------------------------
__device__ __forceinline__ int perm8(int c) {
    int u = c & 7;
    return (c & ~7) | ((u < 4) ? (u << 1) : (((u - 4) << 1) | 1));
}
__device__ __forceinline__ int permH(int k) {
    return (perm8(k >> 1) << 1) | (k & 1);
}
// inverse of perm8 on 0..7: j even -> j/2 ; j odd -> 4 + j/2
__device__ __forceinline__ int inv8(int j) {
    return (j & 1) ? (4 + (j >> 1)) : (j >> 1);
}

// cp.async 16B with zero-fill when sz==0
__device__ __forceinline__ void cp16(void* dst, const void* src, int sz) {
    unsigned d = (unsigned)__cvta_generic_to_shared(dst);
    asm volatile("cp.async.cg.shared.global [%0], [%1], 16, %2;\n"
                 :: "r"(d), "l"(src), "r"(sz));
}

// ---------------------------------------------------------------------------
// Prep A: vectorized x conversion. One thread = one 16-half block.
// Loads 16 fp32 (4 x float4), permutes in registers, stores 2 x uint4.
// ---------------------------------------------------------------------------
#define NXB (BT * HH / 16)        // 196,608 blocks of 16

__global__ void prep_x_kernel(const float* __restrict__ x, __half* __restrict__ xh) {
    const int i = blockIdx.x * 256 + threadIdx.x;   // grid covers NXB exactly
    const float* src = x + (size_t)i * 16;
    float v[16];
#pragma unroll
    for (int j = 0; j < 4; j++) {
        const float4 f = reinterpret_cast<const float4*>(src)[j];
        v[4 * j] = f.x; v[4 * j + 1] = f.y; v[4 * j + 2] = f.z; v[4 * j + 3] = f.w;
    }
    __half o[16];
#pragma unroll
    for (int j = 0; j < 16; j++) {
        const int k = (inv8(j >> 1) << 1) | (j & 1);   // out pos j takes half k
        o[j] = __float2half_rn(v[k]);
    }
    reinterpret_cast<uint4*>(xh + (size_t)i * 16)[0] = *reinterpret_cast<uint4*>(o);
    reinterpret_cast<uint4*>(xh + (size_t)i * 16)[1] = *reinterpret_cast<uint4*>(o + 8);
}

// ---------------------------------------------------------------------------
// Prep B: weight transpose (both convs), scalar scatter.
// w[f,c,tap] -> wt[f*1152 + tap*384 + permH(c)]
// ---------------------------------------------------------------------------
#define NW  (FF * HH * KK3)       // 442,368

__global__ void prep_w_kernel(const float* __restrict__ w1, const float* __restrict__ w2,
                              __half* __restrict__ o1, __half* __restrict__ o2) {
    int i = blockIdx.x * 256 + threadIdx.x;
    const float* w = w1; __half* o = o1;
    if (i >= NW) { i -= NW; w = w2; o = o2; }
    int f   = i / (HH * 3);
    int rem = i % (HH * 3);
    int c   = rem / 3;
    int tap = rem % 3;
    o[f * KKT + tap * HH + permH(c)] = __float2half_rn(w[i]);
}

__device__ __forceinline__ void mma_f16(float c[4], const unsigned a[4], const unsigned b[2]) {
    asm volatile(
        "mma.sync.aligned.m16n8k16.row.col.f32.f16.f16.f32 "
        "{%0,%1,%2,%3}, {%4,%5,%6,%7}, {%8,%9}, {%0,%1,%2,%3};\n"
        : "+f"(c[0]), "+f"(c[1]), "+f"(c[2]), "+f"(c[3])
        : "r"(a[0]), "r"(a[1]), "r"(a[2]), "r"(a[3]), "r"(b[0]), "r"(b[1]));
}

// ---------------------------------------------------------------------------
// Conv-as-GEMM, fp16 m16n8k16, cp.async double-buffered, LDS.64 fragments.
// Grid (6, 64) = 384 CTAs, 256 threads (8 warps: 4M x 2N), 48 KB static smem.
// (exact R10 kernel; residency raised via host-side carveout attribute only)
// ---------------------------------------------------------------------------
__global__ void __launch_bounds__(256) conv_gemm_kernel(
    const __half* __restrict__ Axh, const __half* __restrict__ Bwh,
    const float* __restrict__ bias, float* __restrict__ C) {
    __shared__ __align__(16) uint2 SA[2][BM][16];   // 32 KB
    __shared__ __align__(16) uint2 SB[2][BN][16];   // 16 KB

    const int tid  = threadIdx.x;
    const int lane = tid & 31;
    const int warp = tid >> 5;
    const int m0w  = (warp & 3) * 32;
    const int n0w  = (warp >> 2) * 32;
    const int m0   = blockIdx.y * BM;
    const int f0   = blockIdx.x * BN;
    const int b    = m0 >> 9;
    const int t0   = m0 & (TT - 1);

    const int r = lane >> 2;
    const int q = lane & 3;

    float acc[2][4][4];
#pragma unroll
    for (int mt = 0; mt < 2; mt++)
#pragma unroll
        for (int nt = 0; nt < 4; nt++)
#pragma unroll
            for (int i = 0; i < 4; i++) acc[mt][nt][i] = 0.0f;

    const int amr[4] = { tid >> 3, (tid + 256) >> 3, (tid + 512) >> 3, (tid + 768) >> 3 };
    const int at     = tid & 7;
    const int bnr[2] = { tid >> 3, (tid + 256) >> 3 };

#define LOAD_TILE(KT, BUF) do {                                                \
        const int kk0 = (KT) * BK;                                             \
        const int tap = kk0 / HH;                                              \
        const int c0  = kk0 - tap * HH;                                        \
        _Pragma("unroll")                                                      \
        for (int i = 0; i < 4; i++) {                                          \
            const int m    = amr[i];                                           \
            const int trow = t0 + m + tap - 1;                                 \
            const int ok   = (trow >= 0 && trow < TT);                         \
            const __half* src = Axh +                                          \
                (size_t)((b << 9) + (ok ? trow : 0)) * HH + c0 + 8 * at;       \
            cp16(&SA[BUF][m][(2 * at) ^ ((m & 3) << 2)], src, ok ? 16 : 0);    \
        }                                                                      \
        _Pragma("unroll")                                                      \
        for (int i = 0; i < 2; i++) {                                          \
            const int n = bnr[i];                                              \
            const __half* src = Bwh + (size_t)(f0 + n) * KKT + kk0 + 8 * at;   \
            cp16(&SB[BUF][n][(2 * at) ^ ((n & 3) << 2)], src, 16);             \
        }                                                                      \
        asm volatile("cp.async.commit_group;\n");                              \
    } while (0)

    LOAD_TILE(0, 0);

    for (int kt = 0; kt < NKT; kt++) {
        const int cur = kt & 1;
        if (kt + 1 < NKT) {
            LOAD_TILE(kt + 1, cur ^ 1);
            asm volatile("cp.async.wait_group 1;\n");
        } else {
            asm volatile("cp.async.wait_group 0;\n");
        }
        __syncthreads();

#pragma unroll
        for (int s = 0; s < 4; s++) {
            unsigned a[2][4], bf[4][2];
#pragma unroll
            for (int mt = 0; mt < 2; mt++) {
                const int mr  = m0w + mt * 16 + r;
                const int idx = ((s ^ (mr & 3)) << 2) | q;
                const uint2 va0 = SA[cur][mr][idx];
                const uint2 va1 = SA[cur][mr + 8][idx];
                a[mt][0] = va0.x; a[mt][1] = va1.x; a[mt][2] = va0.y; a[mt][3] = va1.y;
            }
#pragma unroll
            for (int nt = 0; nt < 4; nt++) {
                const int nc  = n0w + nt * 8 + r;
                const uint2 vb = SB[cur][nc][((s ^ (nc & 3)) << 2) | q];
                bf[nt][0] = vb.x; bf[nt][1] = vb.y;
            }
#pragma unroll
            for (int mt = 0; mt < 2; mt++)
#pragma unroll
                for (int nt = 0; nt < 4; nt++)
                    mma_f16(acc[mt][nt], a[mt], bf[nt]);
        }
        __syncthreads();
    }

#pragma unroll
    for (int mt = 0; mt < 2; mt++) {
        const int gm0 = m0 + m0w + mt * 16 + r;
#pragma unroll
        for (int nt = 0; nt < 4; nt++) {
            const int gf = f0 + n0w + nt * 8 + 2 * q;
            const float2 bvv = *reinterpret_cast<const float2*>(bias + gf);
            float2 o0, o1;
            o0.x = acc[mt][nt][0] + bvv.x;
            o0.y = acc[mt][nt][1] + bvv.y;
            o1.x = acc[mt][nt][2] + bvv.x;
            o1.y = acc[mt][nt][3] + bvv.y;
            *reinterpret_cast<float2*>(C + (size_t)gm0 * FF + gf) = o0;
            *reinterpret_cast<float2*>(C + (size_t)(gm0 + 8) * FF + gf) = o1;
        }
    }
#undef LOAD_TILE
}

// ---------------------------------------------------------------------------
__device__ __forceinline__ float warp_sum(float v) {
#pragma unroll
    for (int o = 16; o > 0; o >>= 1) v += __shfl_xor_sync(0xffffffffu, v, o);
    return v;
}

__device__ __forceinline__ float gelu_exact(float y) {
    return 0.5f * y * (1.0f + erff(y * 0.70710678118654752f));
}

// LayerNorm + exact GELU; fp32 in, fp16 pair-permuted out. warp-per-row.
__global__ void __launch_bounds__(256) ln_gelu_kernel(
    const float* __restrict__ h, const float* __restrict__ g, const float* __restrict__ bb,
    __half* __restrict__ oh) {
    const int row  = blockIdx.x * 8 + (threadIdx.x >> 5);
    const int lane = threadIdx.x & 31;
    const float* p = h + (size_t)row * FF;
    __half* po = oh + (size_t)row * FF;
    float v[12];
    float s = 0.0f;
#pragma unroll
    for (int i = 0; i < 12; i++) { v[i] = p[lane + 32 * i]; s += v[i]; }
    const float mu = warp_sum(s) * (1.0f / FF);
    float s2 = 0.0f;
#pragma unroll
    for (int i = 0; i < 12; i++) { v[i] -= mu; s2 += v[i] * v[i]; }
    const float rs = rsqrtf(warp_sum(s2) * (1.0f / FF) + 1e-5f);
#pragma unroll
    for (int i = 0; i < 12; i++) {
        const int c = lane + 32 * i;
        po[permH(c)] = __float2half_rn(gelu_exact(v[i] * rs * g[c] + bb[c]));
    }
}

// LayerNorm + GELU + linear(384->1) + ReLU -> length[row]. warp-per-row.
__global__ void __launch_bounds__(256) ln_gelu_lin_kernel(
    const float* __restrict__ h, const float* __restrict__ g, const float* __restrict__ bb,
    const float* __restrict__ lw, const float* __restrict__ lb, float* __restrict__ lenout) {
    const int row  = blockIdx.x * 8 + (threadIdx.x >> 5);
    const int lane = threadIdx.x & 31;
    const float* p = h + (size_t)row * FF;
    float v[12];
    float s = 0.0f;
#pragma unroll
    for (int i = 0; i < 12; i++) { v[i] = p[lane + 32 * i]; s += v[i]; }
    const float mu = warp_sum(s) * (1.0f / FF);
    float s2 = 0.0f;
#pragma unroll
    for (int i = 0; i < 12; i++) { v[i] -= mu; s2 += v[i] * v[i]; }
    const float rs = rsqrtf(warp_sum(s2) * (1.0f / FF) + 1e-5f);
    float d = 0.0f;
#pragma unroll
    for (int i = 0; i < 12; i++) {
        const int c = lane + 32 * i;
        d += gelu_exact(v[i] * rs * g[c] + bb[c]) * lw[c];
    }
    const float dot = warp_sum(d);
    if (lane == 0) lenout[row] = fmaxf(dot + lb[0], 0.0f);
}

// ---------------------------------------------------------------------------
// Duration scan + token map. One block per batch, 512 threads.
// ---------------------------------------------------------------------------
__global__ void __launch_bounds__(512) build_tok_kernel(
    const float* __restrict__ td, int* __restrict__ tok) {
    __shared__ int sc[TT];
    const int b = blockIdx.x, t = threadIdx.x;
    const int d = (int)rintf(expf(td[b * TT + t]));
    sc[t] = d;
    __syncthreads();
    for (int off = 1; off < TT; off <<= 1) {
        int v = sc[t];
        int add = (t >= off) ? sc[t - off] : 0;
        __syncthreads();
        sc[t] = v + add;
        __syncthreads();
    }
    const int end = sc[t];
    const int start = end - d;
    for (int l = start; l < end; l++) tok[b * LL + l] = t;
    __syncthreads();
    const int total = sc[TT - 1];
    for (int l = total + t; l < LL; l += TT) tok[b * LL + l] = -1;
}

// ---------------------------------------------------------------------------
// Expansion: out[b,l,:] = x[b,tok[b][l],:] (or zeros). float4 per thread.
// ---------------------------------------------------------------------------
__global__ void __launch_bounds__(256) expand_kernel(
    const float* __restrict__ x, const int* __restrict__ tok, float* __restrict__ out) {
    const unsigned idx = blockIdx.x * 256u + threadIdx.x;
    const int h4 = idx % H4;
    const int l  = (idx / H4) & (LL - 1);
    const int b  = idx / (H4 * LL);
    const int t  = tok[b * LL + l];
    float4 v = make_float4(0.f, 0.f, 0.f, 0.f);
    if (t >= 0)
        v = reinterpret_cast<const float4*>(x)[(size_t)(b * TT + t) * H4 + h4];
    reinterpret_cast<float4*>(out)[idx] = v;
}

// ---------------------------------------------------------------------------
extern "C" void kernel_launch(void* const* d_in, const int* in_sizes, int n_in,
                              void* d_out, int out_size) {
    const float* x   = (const float*)d_in[0];
    const float* td  = (const float*)d_in[1];
    const float* w1  = (const float*)d_in[2];
    const float* b1  = (const float*)d_in[3];
    const float* g1  = (const float*)d_in[4];
    const float* bb1 = (const float*)d_in[5];
    const float* w2  = (const float*)d_in[6];
    const float* b2  = (const float*)d_in[7];
    const float* g2  = (const float*)d_in[8];
    const float* bb2 = (const float*)d_in[9];
    const float* lw  = (const float*)d_in[10];
    const float* lb  = (const float*)d_in[11];

    float* out = (float*)d_out;
    float* lenout = out + OUT_OFF;

    __half *wt1p, *wt2p, *xhp, *h1hp;
    float *h1p, *h2p;
    int* tokp;
    cudaGetSymbolAddress((void**)&wt1p, g_wt1h);
    cudaGetSymbolAddress((void**)&wt2p, g_wt2h);
    cudaGetSymbolAddress((void**)&xhp,  g_xh);
    cudaGetSymbolAddress((void**)&h1p,  g_h1);
    cudaGetSymbolAddress((void**)&h1hp, g_h1h);
    cudaGetSymbolAddress((void**)&h2p,  g_h2);
    cudaGetSymbolAddress((void**)&tokp, g_tok);

    // one-time host-side setup: side stream, events, carveout preference
    static cudaStream_t s2 = nullptr;
    static cudaEvent_t evFork = nullptr, evJoin = nullptr;
    if (s2 == nullptr) {
        cudaStreamCreateWithFlags(&s2, cudaStreamNonBlocking);
        cudaEventCreateWithFlags(&evFork, cudaEventDisableTiming);
        cudaEventCreateWithFlags(&evJoin, cudaEventDisableTiming);
        // ask for max shared carveout so 3 x 48KB CTAs can be resident
        cudaFuncSetAttribute(conv_gemm_kernel,
                             cudaFuncAttributePreferredSharedMemoryCarveout,
                             cudaSharedmemCarveoutMaxShared);
    }

    // fork: independent chain (td -> tok -> expand) on s2
    cudaEventRecord(evFork, 0);
    cudaStreamWaitEvent(s2, evFork, 0);
    build_tok_kernel<<<BB, TT, 0, s2>>>(td, tokp);
    expand_kernel<<<(BB * LL * H4) / 256, 256, 0, s2>>>(x, tokp, out);
    cudaEventRecord(evJoin, s2);

    // main chain: prep -> conv1 -> ln -> conv2 -> ln+lin
    prep_x_kernel<<<NXB / 256, 256>>>(x, xhp);
    prep_w_kernel<<<(2 * NW) / 256, 256>>>(w1, w2, wt1p, wt2p);

    dim3 ggrid(FF / BN, BT / BM);   // (6, 64) = 384 CTAs
    conv_gemm_kernel<<<ggrid, 256>>>(xhp, wt1p, b1, h1p);
    ln_gelu_kernel<<<BT / 8, 256>>>(h1p, g1, bb1, h1hp);
    conv_gemm_kernel<<<ggrid, 256>>>(h1hp, wt2p, b2, h2p);
    ln_gelu_lin_kernel<<<BT / 8, 256>>>(h2p, g2, bb2, lw, lb, lenout);

    // join: main stream waits for the expansion branch
    cudaStreamWaitEvent(0, evJoin, 0);
}

// round 15
// speedup vs baseline: 1.5068x; 1.0486x over previous
#include <cuda_runtime.h>
#include <cuda_fp16.h>
#include <math.h>

// Problem constants
#define BB   16
#define TT   512
#define HH   384
#define FF   384
#define KK3  3
#define DMAX 8
#define LL   (TT * DMAX)          // 4096
#define BT   (BB * TT)            // 8192
#define KKT  (HH * KK3)           // 1152 unified reduction dim
#define H4   (HH / 4)             // 96 float4 per row
#define OUT_OFF ((size_t)BB * LL * HH)   // length[] offset in d_out

// GEMM tiling (R10 best config): BM=128, BN=64, BK=64, 256 threads, 2-stage
#define BM 128
#define BN 64
#define BK 64
#define NKT (KKT / BK)            // 18 k-iterations

// Scratch (static device globals; no allocation allowed)
__device__ __half g_wt1h[FF * KKT];     // conv1 weights, f-major, pair-permuted fp16
__device__ __half g_wt2h[FF * KKT];     // conv2 weights, same layout
__device__ __half g_xh[BT * HH];        // x, fp16 + pair-permuted
__device__ float  g_h1[BT * FF];        // conv1 out (fp32)
__device__ __half g_h1h[BT * FF];       // ln_gelu(conv1) fp16 pair-permuted
__device__ float  g_h2[BT * FF];        // conv2 output (fp32)
__device__ int    g_tok[BB * LL];       // token index per expanded position (-1 = pad)

// ---------------------------------------------------------------------------
// half-index permutation: within each 16-half block, k-pairs interleaved
// [0,4,1,5,2,6,3,7] so one LDS.64 yields pairs (q, q+4) = one mma fragment.
// ---------------------------------------------------------------------------
__device__ __forceinline__ int perm8(int c) {
    int u = c & 7;
    return (c & ~7) | ((u < 4) ? (u << 1) : (((u - 4) << 1) | 1));
}
__device__ __forceinline__ int permH(int k) {
    return (perm8(k >> 1) << 1) | (k & 1);
}
// inverse of perm8 on 0..7: j even -> j/2 ; j odd -> 4 + j/2
__device__ __forceinline__ int inv8(int j) {
    return (j & 1) ? (4 + (j >> 1)) : (j >> 1);
}

// cp.async 16B with zero-fill when sz==0
__device__ __forceinline__ void cp16(void* dst, const void* src, int sz) {
    unsigned d = (unsigned)__cvta_generic_to_shared(dst);
    asm volatile("cp.async.cg.shared.global [%0], [%1], 16, %2;\n"
                 :: "r"(d), "l"(src), "r"(sz));
}

// ---------------------------------------------------------------------------
// Prep A: vectorized x conversion. One thread = one 16-half block.
// ---------------------------------------------------------------------------
#define NXB (BT * HH / 16)        // 196,608 blocks of 16

__global__ void prep_x_kernel(const float* __restrict__ x, __half* __restrict__ xh) {
    const int i = blockIdx.x * 256 + threadIdx.x;   // grid covers NXB exactly
    const float* src = x + (size_t)i * 16;
    float v[16];
#pragma unroll
    for (int j = 0; j < 4; j++) {
        const float4 f = reinterpret_cast<const float4*>(src)[j];
        v[4 * j] = f.x; v[4 * j + 1] = f.y; v[4 * j + 2] = f.z; v[4 * j + 3] = f.w;
    }
    __half o[16];
#pragma unroll
    for (int j = 0; j < 16; j++) {
        const int k = (inv8(j >> 1) << 1) | (j & 1);   // out pos j takes half k
        o[j] = __float2half_rn(v[k]);
    }
    reinterpret_cast<uint4*>(xh + (size_t)i * 16)[0] = *reinterpret_cast<uint4*>(o);
    reinterpret_cast<uint4*>(xh + (size_t)i * 16)[1] = *reinterpret_cast<uint4*>(o + 8);
}

// ---------------------------------------------------------------------------
// Prep B: vectorized weight transpose (both convs).
// Thread = (set, f, 16-c block): reads 48 contiguous floats (16 c x 3 taps,
// tap innermost in OIW), writes 3 x 16 permuted halves (2 x STG.128 each).
// w[f,c,tap] -> wt[f*1152 + tap*384 + permH(c)]
// ---------------------------------------------------------------------------
#define NWT (FF * (HH / 16))      // 9,216 threads per weight set
#define NWALL (2 * NWT)           // 18,432 = 72 * 256

__global__ void prep_w_kernel(const float* __restrict__ w1, const float* __restrict__ w2,
                              __half* __restrict__ o1, __half* __restrict__ o2) {
    int i = blockIdx.x * 256 + threadIdx.x;
    const float* w = w1; __half* o = o1;
    if (i >= NWT) { i -= NWT; w = w2; o = o2; }
    const int f  = i / (HH / 16);
    const int cb = i % (HH / 16);
    const float* src = w + (size_t)f * (HH * 3) + cb * 48;
    float v[48];
#pragma unroll
    for (int j = 0; j < 12; j++) {
        const float4 t = reinterpret_cast<const float4*>(src)[j];
        v[4 * j] = t.x; v[4 * j + 1] = t.y; v[4 * j + 2] = t.z; v[4 * j + 3] = t.w;
    }
#pragma unroll
    for (int tap = 0; tap < 3; tap++) {
        __half o16[16];
#pragma unroll
        for (int c = 0; c < 16; c++) {
            const int u = c >> 1;
            const int j = (((u < 4) ? (u << 1) : (((u - 4) << 1) | 1)) << 1) | (c & 1);
            o16[j] = __float2half_rn(v[c * 3 + tap]);
        }
        __half* dst = o + (size_t)f * KKT + tap * HH + cb * 16;
        reinterpret_cast<uint4*>(dst)[0] = *reinterpret_cast<uint4*>(o16);
        reinterpret_cast<uint4*>(dst)[1] = *reinterpret_cast<uint4*>(o16 + 8);
    }
}

__device__ __forceinline__ void mma_f16(float c[4], const unsigned a[4], const unsigned b[2]) {
    asm volatile(
        "mma.sync.aligned.m16n8k16.row.col.f32.f16.f16.f32 "
        "{%0,%1,%2,%3}, {%4,%5,%6,%7}, {%8,%9}, {%0,%1,%2,%3};\n"
        : "+f"(c[0]), "+f"(c[1]), "+f"(c[2]), "+f"(c[3])
        : "r"(a[0]), "r"(a[1]), "r"(a[2]), "r"(a[3]), "r"(b[0]), "r"(b[1]));
}

// ---------------------------------------------------------------------------
// Conv-as-GEMM, fp16 m16n8k16, cp.async double-buffered, LDS.64 fragments.
// Grid (6, 64) = 384 CTAs, 256 threads (8 warps: 4M x 2N), 48 KB static smem.
// ---------------------------------------------------------------------------
__global__ void __launch_bounds__(256) conv_gemm_kernel(
    const __half* __restrict__ Axh, const __half* __restrict__ Bwh,
    const float* __restrict__ bias, float* __restrict__ C) {
    __shared__ __align__(16) uint2 SA[2][BM][16];   // 32 KB
    __shared__ __align__(16) uint2 SB[2][BN][16];   // 16 KB

    const int tid  = threadIdx.x;
    const int lane = tid & 31;
    const int warp = tid >> 5;
    const int m0w  = (warp & 3) * 32;
    const int n0w  = (warp >> 2) * 32;
    const int m0   = blockIdx.y * BM;
    const int f0   = blockIdx.x * BN;
    const int b    = m0 >> 9;
    const int t0   = m0 & (TT - 1);

    const int r = lane >> 2;
    const int q = lane & 3;

    float acc[2][4][4];
#pragma unroll
    for (int mt = 0; mt < 2; mt++)
#pragma unroll
        for (int nt = 0; nt < 4; nt++)
#pragma unroll
            for (int i = 0; i < 4; i++) acc[mt][nt][i] = 0.0f;

    const int amr[4] = { tid >> 3, (tid + 256) >> 3, (tid + 512) >> 3, (tid + 768) >> 3 };
    const int at     = tid & 7;
    const int bnr[2] = { tid >> 3, (tid + 256) >> 3 };

#define LOAD_TILE(KT, BUF) do {                                                \
        const int kk0 = (KT) * BK;                                             \
        const int tap = kk0 / HH;                                              \
        const int c0  = kk0 - tap * HH;                                        \
        _Pragma("unroll")                                                      \
        for (int i = 0; i < 4; i++) {                                          \
            const int m    = amr[i];                                           \
            const int trow = t0 + m + tap - 1;                                 \
            const int ok   = (trow >= 0 && trow < TT);                         \
            const __half* src = Axh +                                          \
                (size_t)((b << 9) + (ok ? trow : 0)) * HH + c0 + 8 * at;       \
            cp16(&SA[BUF][m][(2 * at) ^ ((m & 3) << 2)], src, ok ? 16 : 0);    \
        }                                                                      \
        _Pragma("unroll")                                                      \
        for (int i = 0; i < 2; i++) {                                          \
            const int n = bnr[i];                                              \
            const __half* src = Bwh + (size_t)(f0 + n) * KKT + kk0 + 8 * at;   \
            cp16(&SB[BUF][n][(2 * at) ^ ((n & 3) << 2)], src, 16);             \
        }                                                                      \
        asm volatile("cp.async.commit_group;\n");                              \
    } while (0)

    LOAD_TILE(0, 0);

    for (int kt = 0; kt < NKT; kt++) {
        const int cur = kt & 1;
        if (kt + 1 < NKT) {
            LOAD_TILE(kt + 1, cur ^ 1);
            asm volatile("cp.async.wait_group 1;\n");
        } else {
            asm volatile("cp.async.wait_group 0;\n");
        }
        __syncthreads();

#pragma unroll
        for (int s = 0; s < 4; s++) {
            unsigned a[2][4], bf[4][2];
#pragma unroll
            for (int mt = 0; mt < 2; mt++) {
                const int mr  = m0w + mt * 16 + r;
                const int idx = ((s ^ (mr & 3)) << 2) | q;
                const uint2 va0 = SA[cur][mr][idx];
                const uint2 va1 = SA[cur][mr + 8][idx];
                a[mt][0] = va0.x; a[mt][1] = va1.x; a[mt][2] = va0.y; a[mt][3] = va1.y;
            }
#pragma unroll
            for (int nt = 0; nt < 4; nt++) {
                const int nc  = n0w + nt * 8 + r;
                const uint2 vb = SB[cur][nc][((s ^ (nc & 3)) << 2) | q];
                bf[nt][0] = vb.x; bf[nt][1] = vb.y;
            }
#pragma unroll
            for (int mt = 0; mt < 2; mt++)
#pragma unroll
                for (int nt = 0; nt < 4; nt++)
                    mma_f16(acc[mt][nt], a[mt], bf[nt]);
        }
        __syncthreads();
    }

#pragma unroll
    for (int mt = 0; mt < 2; mt++) {
        const int gm0 = m0 + m0w + mt * 16 + r;
#pragma unroll
        for (int nt = 0; nt < 4; nt++) {
            const int gf = f0 + n0w + nt * 8 + 2 * q;
            const float2 bvv = *reinterpret_cast<const float2*>(bias + gf);
            float2 o0, o1;
            o0.x = acc[mt][nt][0] + bvv.x;
            o0.y = acc[mt][nt][1] + bvv.y;
            o1.x = acc[mt][nt][2] + bvv.x;
            o1.y = acc[mt][nt][3] + bvv.y;
            *reinterpret_cast<float2*>(C + (size_t)gm0 * FF + gf) = o0;
            *reinterpret_cast<float2*>(C + (size_t)(gm0 + 8) * FF + gf) = o1;
        }
    }
#undef LOAD_TILE
}

// ---------------------------------------------------------------------------
__device__ __forceinline__ float warp_sum(float v) {
#pragma unroll
    for (int o = 16; o > 0; o >>= 1) v += __shfl_xor_sync(0xffffffffu, v, o);
    return v;
}

__device__ __forceinline__ float gelu_exact(float y) {
    return 0.5f * y * (1.0f + erff(y * 0.70710678118654752f));
}

// LayerNorm + exact GELU; fp32 in, fp16 pair-permuted out. warp-per-row.
__global__ void __launch_bounds__(256) ln_gelu_kernel(
    const float* __restrict__ h, const float* __restrict__ g, const float* __restrict__ bb,
    __half* __restrict__ oh) {
    const int row  = blockIdx.x * 8 + (threadIdx.x >> 5);
    const int lane = threadIdx.x & 31;
    const float* p = h + (size_t)row * FF;
    __half* po = oh + (size_t)row * FF;
    float v[12];
    float s = 0.0f;
#pragma unroll
    for (int i = 0; i < 12; i++) { v[i] = p[lane + 32 * i]; s += v[i]; }
    const float mu = warp_sum(s) * (1.0f / FF);
    float s2 = 0.0f;
#pragma unroll
    for (int i = 0; i < 12; i++) { v[i] -= mu; s2 += v[i] * v[i]; }
    const float rs = rsqrtf(warp_sum(s2) * (1.0f / FF) + 1e-5f);
#pragma unroll
    for (int i = 0; i < 12; i++) {
        const int c = lane + 32 * i;
        po[permH(c)] = __float2half_rn(gelu_exact(v[i] * rs * g[c] + bb[c]));
    }
}

// LayerNorm + GELU + linear(384->1) + ReLU -> length[row]. warp-per-row.
__global__ void __launch_bounds__(256) ln_gelu_lin_kernel(
    const float* __restrict__ h, const float* __restrict__ g, const float* __restrict__ bb,
    const float* __restrict__ lw, const float* __restrict__ lb, float* __restrict__ lenout) {
    const int row  = blockIdx.x * 8 + (threadIdx.x >> 5);
    const int lane = threadIdx.x & 31;
    const float* p = h + (size_t)row * FF;
    float v[12];
    float s = 0.0f;
#pragma unroll
    for (int i = 0; i < 12; i++) { v[i] = p[lane + 32 * i]; s += v[i]; }
    const float mu = warp_sum(s) * (1.0f / FF);
    float s2 = 0.0f;
#pragma unroll
    for (int i = 0; i < 12; i++) { v[i] -= mu; s2 += v[i] * v[i]; }
    const float rs = rsqrtf(warp_sum(s2) * (1.0f / FF) + 1e-5f);
    float d = 0.0f;
#pragma unroll
    for (int i = 0; i < 12; i++) {
        const int c = lane + 32 * i;
        d += gelu_exact(v[i] * rs * g[c] + bb[c]) * lw[c];
    }
    const float dot = warp_sum(d);
    if (lane == 0) lenout[row] = fmaxf(dot + lb[0], 0.0f);
}

// ---------------------------------------------------------------------------
// Duration scan + token map. One block per batch, 512 threads.
// ---------------------------------------------------------------------------
__global__ void __launch_bounds__(512) build_tok_kernel(
    const float* __restrict__ td, int* __restrict__ tok) {
    __shared__ int sc[TT];
    const int b = blockIdx.x, t = threadIdx.x;
    const int d = (int)rintf(expf(td[b * TT + t]));
    sc[t] = d;
    __syncthreads();
    for (int off = 1; off < TT; off <<= 1) {
        int v = sc[t];
        int add = (t >= off) ? sc[t - off] : 0;
        __syncthreads();
        sc[t] = v + add;
        __syncthreads();
    }
    const int end = sc[t];
    const int start = end - d;
    for (int l = start; l < end; l++) tok[b * LL + l] = t;
    __syncthreads();
    const int total = sc[TT - 1];
    for (int l = total + t; l < LL; l += TT) tok[b * LL + l] = -1;
}

// ---------------------------------------------------------------------------
// Expansion: out[b,l,:] = x[b,tok[b][l],:] (or zeros). float4 per thread.
// ---------------------------------------------------------------------------
__global__ void __launch_bounds__(256) expand_kernel(
    const float* __restrict__ x, const int* __restrict__ tok, float* __restrict__ out) {
    const unsigned idx = blockIdx.x * 256u + threadIdx.x;
    const int h4 = idx % H4;
    const int l  = (idx / H4) & (LL - 1);
    const int b  = idx / (H4 * LL);
    const int t  = tok[b * LL + l];
    float4 v = make_float4(0.f, 0.f, 0.f, 0.f);
    if (t >= 0)
        v = reinterpret_cast<const float4*>(x)[(size_t)(b * TT + t) * H4 + h4];
    reinterpret_cast<float4*>(out)[idx] = v;
}

// ---------------------------------------------------------------------------
extern "C" void kernel_launch(void* const* d_in, const int* in_sizes, int n_in,
                              void* d_out, int out_size) {
    const float* x   = (const float*)d_in[0];
    const float* td  = (const float*)d_in[1];
    const float* w1  = (const float*)d_in[2];
    const float* b1  = (const float*)d_in[3];
    const float* g1  = (const float*)d_in[4];
    const float* bb1 = (const float*)d_in[5];
    const float* w2  = (const float*)d_in[6];
    const float* b2  = (const float*)d_in[7];
    const float* g2  = (const float*)d_in[8];
    const float* bb2 = (const float*)d_in[9];
    const float* lw  = (const float*)d_in[10];
    const float* lb  = (const float*)d_in[11];

    float* out = (float*)d_out;
    float* lenout = out + OUT_OFF;

    __half *wt1p, *wt2p, *xhp, *h1hp;
    float *h1p, *h2p;
    int* tokp;
    cudaGetSymbolAddress((void**)&wt1p, g_wt1h);
    cudaGetSymbolAddress((void**)&wt2p, g_wt2h);
    cudaGetSymbolAddress((void**)&xhp,  g_xh);
    cudaGetSymbolAddress((void**)&h1p,  g_h1);
    cudaGetSymbolAddress((void**)&h1hp, g_h1h);
    cudaGetSymbolAddress((void**)&h2p,  g_h2);
    cudaGetSymbolAddress((void**)&tokp, g_tok);

    // one-time host-side setup: side stream + bridge events (no device mem)
    static cudaStream_t s2 = nullptr;
    static cudaEvent_t evFork = nullptr, evW = nullptr, evJoin = nullptr;
    if (s2 == nullptr) {
        cudaStreamCreateWithFlags(&s2, cudaStreamNonBlocking);
        cudaEventCreateWithFlags(&evFork, cudaEventDisableTiming);
        cudaEventCreateWithFlags(&evW,    cudaEventDisableTiming);
        cudaEventCreateWithFlags(&evJoin, cudaEventDisableTiming);
    }

    // fork: s2 runs weight prep first (needed by conv1), then tok/expand chain
    cudaEventRecord(evFork, 0);
    cudaStreamWaitEvent(s2, evFork, 0);
    prep_w_kernel<<<NWALL / 256, 256, 0, s2>>>(w1, w2, wt1p, wt2p);
    cudaEventRecord(evW, s2);
    build_tok_kernel<<<BB, TT, 0, s2>>>(td, tokp);
    expand_kernel<<<(BB * LL * H4) / 256, 256, 0, s2>>>(x, tokp, out);
    cudaEventRecord(evJoin, s2);

    // main chain: prep_x (parallel with prep_w) -> conv1 -> ln -> conv2 -> ln+lin
    prep_x_kernel<<<NXB / 256, 256>>>(x, xhp);
    cudaStreamWaitEvent(0, evW, 0);

    dim3 ggrid(FF / BN, BT / BM);   // (6, 64) = 384 CTAs
    conv_gemm_kernel<<<ggrid, 256>>>(xhp, wt1p, b1, h1p);
    ln_gelu_kernel<<<BT / 8, 256>>>(h1p, g1, bb1, h1hp);
    conv_gemm_kernel<<<ggrid, 256>>>(h1hp, wt2p, b2, h2p);
    ln_gelu_lin_kernel<<<BT / 8, 256>>>(h2p, g2, bb2, lw, lb, lenout);

    // join: main stream waits for the expansion branch
    cudaStreamWaitEvent(0, evJoin, 0);
}

// round 16
// speedup vs baseline: 1.6938x; 1.1241x over previous
#include <cuda_runtime.h>
#include <cuda_fp16.h>
#include <math.h>

// Problem constants
#define BB   16
#define TT   512
#define HH   384
#define FF   384
#define KK3  3
#define DMAX 8
#define LL   (TT * DMAX)          // 4096
#define BT   (BB * TT)            // 8192
#define KKT  (HH * KK3)           // 1152 unified reduction dim
#define H4   (HH / 4)             // 96 float4 per row
#define OUT_OFF ((size_t)BB * LL * HH)   // length[] offset in d_out

// GEMM tiling (best config): BM=128, BN=64, BK=64, 256 threads, 2-stage
#define BM 128
#define BN 64
#define BK 64
#define NKT (KKT / BK)            // 18 k-iterations

// Scratch (static device globals; no allocation allowed)
__device__ __half g_wt1h[FF * KKT];     // conv1 weights, f-major, pair-permuted fp16
__device__ __half g_wt2h[FF * KKT];     // conv2 weights, same layout
__device__ __half g_xh[BT * HH];        // x, fp16 + pair-permuted
__device__ float  g_h1[BT * FF];        // conv1 out (fp32)
__device__ __half g_h1h[BT * FF];       // ln_gelu(conv1) fp16 pair-permuted
__device__ float  g_h2[BT * FF];        // conv2 output (fp32)
__device__ int    g_tok[BB * LL];       // token index per expanded position (-1 = pad)

// ---------------------------------------------------------------------------
// half-index permutation: within each 16-half block, k-pairs interleaved
// [0,4,1,5,2,6,3,7] so one LDS.64 yields pairs (q, q+4) = one mma fragment.
// permH(2p) = 2*perm8(p), permH(2p+1) = 2*perm8(p)+1  (pairs stay contiguous)
// ---------------------------------------------------------------------------
__device__ __forceinline__ int perm8(int c) {
    int u = c & 7;
    return (c & ~7) | ((u < 4) ? (u << 1) : (((u - 4) << 1) | 1));
}
__device__ __forceinline__ int permH(int k) {
    return (perm8(k >> 1) << 1) | (k & 1);
}
// inverse of perm8 on 0..7: j even -> j/2 ; j odd -> 4 + j/2
__device__ __forceinline__ int inv8(int j) {
    return (j & 1) ? (4 + (j >> 1)) : (j >> 1);
}

// cp.async 16B with zero-fill when sz==0
__device__ __forceinline__ void cp16(void* dst, const void* src, int sz) {
    unsigned d = (unsigned)__cvta_generic_to_shared(dst);
    asm volatile("cp.async.cg.shared.global [%0], [%1], 16, %2;\n"
                 :: "r"(d), "l"(src), "r"(sz));
}

// ---------------------------------------------------------------------------
// Prep A: vectorized x conversion. One thread = one 16-half block.
// Launched twice (split across streams) via base offset in 16-blocks.
// ---------------------------------------------------------------------------
#define NXB (BT * HH / 16)        // 196,608 blocks of 16
#define NXA (2 * NXB / 3)         // 131,072 on main stream (512 blocks)
#define NXS (NXB - NXA)           // 65,536 on side stream (256 blocks)

__global__ void prep_x_kernel(const float* __restrict__ x, __half* __restrict__ xh,
                              int base) {
    const int i = base + blockIdx.x * 256 + threadIdx.x;
    const float* src = x + (size_t)i * 16;
    float v[16];
#pragma unroll
    for (int j = 0; j < 4; j++) {
        const float4 f = reinterpret_cast<const float4*>(src)[j];
        v[4 * j] = f.x; v[4 * j + 1] = f.y; v[4 * j + 2] = f.z; v[4 * j + 3] = f.w;
    }
    __half o[16];
#pragma unroll
    for (int j = 0; j < 16; j++) {
        const int k = (inv8(j >> 1) << 1) | (j & 1);   // out pos j takes half k
        o[j] = __float2half_rn(v[k]);
    }
    reinterpret_cast<uint4*>(xh + (size_t)i * 16)[0] = *reinterpret_cast<uint4*>(o);
    reinterpret_cast<uint4*>(xh + (size_t)i * 16)[1] = *reinterpret_cast<uint4*>(o + 8);
}

// ---------------------------------------------------------------------------
// Prep B: vectorized weight transpose (both convs).
// w[f,c,tap] -> wt[f*1152 + tap*384 + permH(c)]
// ---------------------------------------------------------------------------
#define NWT (FF * (HH / 16))      // 9,216 threads per weight set
#define NWALL (2 * NWT)           // 18,432 = 72 * 256

__global__ void prep_w_kernel(const float* __restrict__ w1, const float* __restrict__ w2,
                              __half* __restrict__ o1, __half* __restrict__ o2) {
    int i = blockIdx.x * 256 + threadIdx.x;
    const float* w = w1; __half* o = o1;
    if (i >= NWT) { i -= NWT; w = w2; o = o2; }
    const int f  = i / (HH / 16);
    const int cb = i % (HH / 16);
    const float* src = w + (size_t)f * (HH * 3) + cb * 48;
    float v[48];
#pragma unroll
    for (int j = 0; j < 12; j++) {
        const float4 t = reinterpret_cast<const float4*>(src)[j];
        v[4 * j] = t.x; v[4 * j + 1] = t.y; v[4 * j + 2] = t.z; v[4 * j + 3] = t.w;
    }
#pragma unroll
    for (int tap = 0; tap < 3; tap++) {
        __half o16[16];
#pragma unroll
        for (int c = 0; c < 16; c++) {
            const int u = c >> 1;
            const int j = (((u < 4) ? (u << 1) : (((u - 4) << 1) | 1)) << 1) | (c & 1);
            o16[j] = __float2half_rn(v[c * 3 + tap]);
        }
        __half* dst = o + (size_t)f * KKT + tap * HH + cb * 16;
        reinterpret_cast<uint4*>(dst)[0] = *reinterpret_cast<uint4*>(o16);
        reinterpret_cast<uint4*>(dst)[1] = *reinterpret_cast<uint4*>(o16 + 8);
    }
}

__device__ __forceinline__ void mma_f16(float c[4], const unsigned a[4], const unsigned b[2]) {
    asm volatile(
        "mma.sync.aligned.m16n8k16.row.col.f32.f16.f16.f32 "
        "{%0,%1,%2,%3}, {%4,%5,%6,%7}, {%8,%9}, {%0,%1,%2,%3};\n"
        : "+f"(c[0]), "+f"(c[1]), "+f"(c[2]), "+f"(c[3])
        : "r"(a[0]), "r"(a[1]), "r"(a[2]), "r"(a[3]), "r"(b[0]), "r"(b[1]));
}

// ---------------------------------------------------------------------------
// Conv-as-GEMM, fp16 m16n8k16, cp.async double-buffered, LDS.64 fragments.
// Grid (6, 64) = 384 CTAs, 256 threads (8 warps: 4M x 2N), 48 KB static smem.
// ---------------------------------------------------------------------------
__global__ void __launch_bounds__(256) conv_gemm_kernel(
    const __half* __restrict__ Axh, const __half* __restrict__ Bwh,
    const float* __restrict__ bias, float* __restrict__ C) {
    __shared__ __align__(16) uint2 SA[2][BM][16];   // 32 KB
    __shared__ __align__(16) uint2 SB[2][BN][16];   // 16 KB

    const int tid  = threadIdx.x;
    const int lane = tid & 31;
    const int warp = tid >> 5;
    const int m0w  = (warp & 3) * 32;
    const int n0w  = (warp >> 2) * 32;
    const int m0   = blockIdx.y * BM;
    const int f0   = blockIdx.x * BN;
    const int b    = m0 >> 9;
    const int t0   = m0 & (TT - 1);

    const int r = lane >> 2;
    const int q = lane & 3;

    float acc[2][4][4];
#pragma unroll
    for (int mt = 0; mt < 2; mt++)
#pragma unroll
        for (int nt = 0; nt < 4; nt++)
#pragma unroll
            for (int i = 0; i < 4; i++) acc[mt][nt][i] = 0.0f;

    const int amr[4] = { tid >> 3, (tid + 256) >> 3, (tid + 512) >> 3, (tid + 768) >> 3 };
    const int at     = tid & 7;
    const int bnr[2] = { tid >> 3, (tid + 256) >> 3 };

#define LOAD_TILE(KT, BUF) do {                                                \
        const int kk0 = (KT) * BK;                                             \
        const int tap = kk0 / HH;                                              \
        const int c0  = kk0 - tap * HH;                                        \
        _Pragma("unroll")                                                      \
        for (int i = 0; i < 4; i++) {                                          \
            const int m    = amr[i];                                           \
            const int trow = t0 + m + tap - 1;                                 \
            const int ok   = (trow >= 0 && trow < TT);                         \
            const __half* src = Axh +                                          \
                (size_t)((b << 9) + (ok ? trow : 0)) * HH + c0 + 8 * at;       \
            cp16(&SA[BUF][m][(2 * at) ^ ((m & 3) << 2)], src, ok ? 16 : 0);    \
        }                                                                      \
        _Pragma("unroll")                                                      \
        for (int i = 0; i < 2; i++) {                                          \
            const int n = bnr[i];                                              \
            const __half* src = Bwh + (size_t)(f0 + n) * KKT + kk0 + 8 * at;   \
            cp16(&SB[BUF][n][(2 * at) ^ ((n & 3) << 2)], src, 16);             \
        }                                                                      \
        asm volatile("cp.async.commit_group;\n");                              \
    } while (0)

    LOAD_TILE(0, 0);

    for (int kt = 0; kt < NKT; kt++) {
        const int cur = kt & 1;
        if (kt + 1 < NKT) {
            LOAD_TILE(kt + 1, cur ^ 1);
            asm volatile("cp.async.wait_group 1;\n");
        } else {
            asm volatile("cp.async.wait_group 0;\n");
        }
        __syncthreads();

#pragma unroll
        for (int s = 0; s < 4; s++) {
            unsigned a[2][4], bf[4][2];
#pragma unroll
            for (int mt = 0; mt < 2; mt++) {
                const int mr  = m0w + mt * 16 + r;
                const int idx = ((s ^ (mr & 3)) << 2) | q;
                const uint2 va0 = SA[cur][mr][idx];
                const uint2 va1 = SA[cur][mr + 8][idx];
                a[mt][0] = va0.x; a[mt][1] = va1.x; a[mt][2] = va0.y; a[mt][3] = va1.y;
            }
#pragma unroll
            for (int nt = 0; nt < 4; nt++) {
                const int nc  = n0w + nt * 8 + r;
                const uint2 vb = SB[cur][nc][((s ^ (nc & 3)) << 2) | q];
                bf[nt][0] = vb.x; bf[nt][1] = vb.y;
            }
#pragma unroll
            for (int mt = 0; mt < 2; mt++)
#pragma unroll
                for (int nt = 0; nt < 4; nt++)
                    mma_f16(acc[mt][nt], a[mt], bf[nt]);
        }
        __syncthreads();
    }

#pragma unroll
    for (int mt = 0; mt < 2; mt++) {
        const int gm0 = m0 + m0w + mt * 16 + r;
#pragma unroll
        for (int nt = 0; nt < 4; nt++) {
            const int gf = f0 + n0w + nt * 8 + 2 * q;
            const float2 bvv = *reinterpret_cast<const float2*>(bias + gf);
            float2 o0, o1;
            o0.x = acc[mt][nt][0] + bvv.x;
            o0.y = acc[mt][nt][1] + bvv.y;
            o1.x = acc[mt][nt][2] + bvv.x;
            o1.y = acc[mt][nt][3] + bvv.y;
            *reinterpret_cast<float2*>(C + (size_t)gm0 * FF + gf) = o0;
            *reinterpret_cast<float2*>(C + (size_t)(gm0 + 8) * FF + gf) = o1;
        }
    }
#undef LOAD_TILE
}

// ---------------------------------------------------------------------------
__device__ __forceinline__ float warp_sum(float v) {
#pragma unroll
    for (int o = 16; o > 0; o >>= 1) v += __shfl_xor_sync(0xffffffffu, v, o);
    return v;
}

__device__ __forceinline__ float gelu_exact(float y) {
    return 0.5f * y * (1.0f + erff(y * 0.70710678118654752f));
}

// LayerNorm + exact GELU; fp32 in, fp16 pair-permuted out. warp-per-row,
// pairwise: 6 x LDG.64 + 6 x STG.32 per lane (192 pairs per row).
__global__ void __launch_bounds__(256) ln_gelu_kernel(
    const float* __restrict__ h, const float* __restrict__ g, const float* __restrict__ bb,
    __half* __restrict__ oh) {
    const int row  = blockIdx.x * 8 + (threadIdx.x >> 5);
    const int lane = threadIdx.x & 31;
    const float2* p2 = reinterpret_cast<const float2*>(h + (size_t)row * FF);
    const float2* g2 = reinterpret_cast<const float2*>(g);
    const float2* b2 = reinterpret_cast<const float2*>(bb);
    __half2* po2 = reinterpret_cast<__half2*>(oh + (size_t)row * FF);
    float2 v[6];
    float s = 0.0f;
#pragma unroll
    for (int i = 0; i < 6; i++) { v[i] = p2[lane + 32 * i]; s += v[i].x + v[i].y; }
    const float mu = warp_sum(s) * (1.0f / FF);
    float s2 = 0.0f;
#pragma unroll
    for (int i = 0; i < 6; i++) {
        v[i].x -= mu; v[i].y -= mu;
        s2 += v[i].x * v[i].x + v[i].y * v[i].y;
    }
    const float rs = rsqrtf(warp_sum(s2) * (1.0f / FF) + 1e-5f);
#pragma unroll
    for (int i = 0; i < 6; i++) {
        const int p = lane + 32 * i;           // pair index 0..191
        const float2 gg = g2[p];
        const float2 bv = b2[p];
        const float y0 = gelu_exact(v[i].x * rs * gg.x + bv.x);
        const float y1 = gelu_exact(v[i].y * rs * gg.y + bv.y);
        const int dp = (p & ~7) | perm8(p & 7);   // permuted pair position
        po2[dp] = __floats2half2_rn(y0, y1);
    }
}

// LayerNorm + GELU + linear(384->1) + ReLU -> length[row]. warp-per-row, pairwise.
__global__ void __launch_bounds__(256) ln_gelu_lin_kernel(
    const float* __restrict__ h, const float* __restrict__ g, const float* __restrict__ bb,
    const float* __restrict__ lw, const float* __restrict__ lb, float* __restrict__ lenout) {
    const int row  = blockIdx.x * 8 + (threadIdx.x >> 5);
    const int lane = threadIdx.x & 31;
    const float2* p2 = reinterpret_cast<const float2*>(h + (size_t)row * FF);
    const float2* g2 = reinterpret_cast<const float2*>(g);
    const float2* b2 = reinterpret_cast<const float2*>(bb);
    const float2* l2 = reinterpret_cast<const float2*>(lw);
    float2 v[6];
    float s = 0.0f;
#pragma unroll
    for (int i = 0; i < 6; i++) { v[i] = p2[lane + 32 * i]; s += v[i].x + v[i].y; }
    const float mu = warp_sum(s) * (1.0f / FF);
    float s2 = 0.0f;
#pragma unroll
    for (int i = 0; i < 6; i++) {
        v[i].x -= mu; v[i].y -= mu;
        s2 += v[i].x * v[i].x + v[i].y * v[i].y;
    }
    const float rs = rsqrtf(warp_sum(s2) * (1.0f / FF) + 1e-5f);
    float d = 0.0f;
#pragma unroll
    for (int i = 0; i < 6; i++) {
        const int p = lane + 32 * i;
        const float2 gg = g2[p];
        const float2 bv = b2[p];
        const float2 lv = l2[p];
        d += gelu_exact(v[i].x * rs * gg.x + bv.x) * lv.x;
        d += gelu_exact(v[i].y * rs * gg.y + bv.y) * lv.y;
    }
    const float dot = warp_sum(d);
    if (lane == 0) lenout[row] = fmaxf(dot + lb[0], 0.0f);
}

// ---------------------------------------------------------------------------
// Duration scan + token map. One block per batch, 512 threads.
// ---------------------------------------------------------------------------
__global__ void __launch_bounds__(512) build_tok_kernel(
    const float* __restrict__ td, int* __restrict__ tok) {
    __shared__ int sc[TT];
    const int b = blockIdx.x, t = threadIdx.x;
    const int d = (int)rintf(expf(td[b * TT + t]));
    sc[t] = d;
    __syncthreads();
    for (int off = 1; off < TT; off <<= 1) {
        int v = sc[t];
        int add = (t >= off) ? sc[t - off] : 0;
        __syncthreads();
        sc[t] = v + add;
        __syncthreads();
    }
    const int end = sc[t];
    const int start = end - d;
    for (int l = start; l < end; l++) tok[b * LL + l] = t;
    __syncthreads();
    const int total = sc[TT - 1];
    for (int l = total + t; l < LL; l += TT) tok[b * LL + l] = -1;
}

// ---------------------------------------------------------------------------
// Expansion: out[b,l,:] = x[b,tok[b][l],:] (or zeros). float4 per thread.
// ---------------------------------------------------------------------------
__global__ void __launch_bounds__(256) expand_kernel(
    const float* __restrict__ x, const int* __restrict__ tok, float* __restrict__ out) {
    const unsigned idx = blockIdx.x * 256u + threadIdx.x;
    const int h4 = idx % H4;
    const int l  = (idx / H4) & (LL - 1);
    const int b  = idx / (H4 * LL);
    const int t  = tok[b * LL + l];
    float4 v = make_float4(0.f, 0.f, 0.f, 0.f);
    if (t >= 0)
        v = reinterpret_cast<const float4*>(x)[(size_t)(b * TT + t) * H4 + h4];
    reinterpret_cast<float4*>(out)[idx] = v;
}

// ---------------------------------------------------------------------------
extern "C" void kernel_launch(void* const* d_in, const int* in_sizes, int n_in,
                              void* d_out, int out_size) {
    const float* x   = (const float*)d_in[0];
    const float* td  = (const float*)d_in[1];
    const float* w1  = (const float*)d_in[2];
    const float* b1  = (const float*)d_in[3];
    const float* g1  = (const float*)d_in[4];
    const float* bb1 = (const float*)d_in[5];
    const float* w2  = (const float*)d_in[6];
    const float* b2  = (const float*)d_in[7];
    const float* g2  = (const float*)d_in[8];
    const float* bb2 = (const float*)d_in[9];
    const float* lw  = (const float*)d_in[10];
    const float* lb  = (const float*)d_in[11];

    float* out = (float*)d_out;
    float* lenout = out + OUT_OFF;

    __half *wt1p, *wt2p, *xhp, *h1hp;
    float *h1p, *h2p;
    int* tokp;
    cudaGetSymbolAddress((void**)&wt1p, g_wt1h);
    cudaGetSymbolAddress((void**)&wt2p, g_wt2h);
    cudaGetSymbolAddress((void**)&xhp,  g_xh);
    cudaGetSymbolAddress((void**)&h1p,  g_h1);
    cudaGetSymbolAddress((void**)&h1hp, g_h1h);
    cudaGetSymbolAddress((void**)&h2p,  g_h2);
    cudaGetSymbolAddress((void**)&tokp, g_tok);

    // one-time host-side setup: side stream + bridge events (no device mem)
    static cudaStream_t s2 = nullptr;
    static cudaEvent_t evFork = nullptr, evW = nullptr, evJoin = nullptr;
    if (s2 == nullptr) {
        cudaStreamCreateWithFlags(&s2, cudaStreamNonBlocking);
        cudaEventCreateWithFlags(&evFork, cudaEventDisableTiming);
        cudaEventCreateWithFlags(&evW,    cudaEventDisableTiming);
        cudaEventCreateWithFlags(&evJoin, cudaEventDisableTiming);
    }

    // fork: s2 runs weight prep + 1/3 of x prep, then the tok/expand chain
    cudaEventRecord(evFork, 0);
    cudaStreamWaitEvent(s2, evFork, 0);
    prep_w_kernel<<<NWALL / 256, 256, 0, s2>>>(w1, w2, wt1p, wt2p);
    prep_x_kernel<<<NXS / 256, 256, 0, s2>>>(x, xhp, NXA);
    cudaEventRecord(evW, s2);
    build_tok_kernel<<<BB, TT, 0, s2>>>(td, tokp);
    expand_kernel<<<(BB * LL * H4) / 256, 256, 0, s2>>>(x, tokp, out);
    cudaEventRecord(evJoin, s2);

    // main chain: 2/3 of x prep (parallel with s2 prep) -> convs + LNs
    prep_x_kernel<<<NXA / 256, 256>>>(x, xhp, 0);
    cudaStreamWaitEvent(0, evW, 0);

    dim3 ggrid(FF / BN, BT / BM);   // (6, 64) = 384 CTAs
    conv_gemm_kernel<<<ggrid, 256>>>(xhp, wt1p, b1, h1p);
    ln_gelu_kernel<<<BT / 8, 256>>>(h1p, g1, bb1, h1hp);
    conv_gemm_kernel<<<ggrid, 256>>>(h1hp, wt2p, b2, h2p);
    ln_gelu_lin_kernel<<<BT / 8, 256>>>(h2p, g2, bb2, lw, lb, lenout);

    // join: main stream waits for the expansion branch
    cudaStreamWaitEvent(0, evJoin, 0);
}